// round 16
// baseline (speedup 1.0000x reference)
#include <cuda_runtime.h>
#include <math.h>

#define C_IN   64
#define FD     8
#define OUTC   9
#define KW     5
#define HEIGHT 4096
#define BATCH  32
#define NTOK   (BATCH * HEIGHT)      // 131072 tokens (b,h)
#define HALF   36
#define MIN_EIG 0.001f
#define NSWEEP 4

// SoA scratch: sigma[e][token]
__device__ float g_sigma[HALF * NTOK];

typedef unsigned long long ull;

__device__ __forceinline__ ull pk(float lo, float hi) {
    ull r; asm("mov.b64 %0, {%1, %2};" : "=l"(r) : "f"(lo), "f"(hi)); return r;
}
__device__ __forceinline__ void upk(ull v, float& lo, float& hi) {
    asm("mov.b64 {%0, %1}, %2;" : "=f"(lo), "=f"(hi) : "l"(v));
}
__device__ __forceinline__ ull fma2(ull a, ull b, ull c) {
    ull d; asm("fma.rn.f32x2 %0, %1, %2, %3;" : "=l"(d) : "l"(a), "l"(b), "l"(c)); return d;
}
__device__ __forceinline__ ull mul2(ull a, ull b) {
    ull d; asm("mul.rn.f32x2 %0, %1, %2;" : "=l"(d) : "l"(a), "l"(b)); return d;
}
__device__ __forceinline__ float softplus(float v) {
    return v > 20.0f ? v : log1pf(expf(v));
}

// ---------------------------------------------------------------------------
// Conv channel step: TWO tokens per thread, f32x2 packed ACROSS tokens
// (xp[m] = (x_tok0[m], x_tok1[m]); weights broadcast-packed). Halves FMA2
// count per token vs feature-packing. Output-channel range [OB,OE) per warp.
// ---------------------------------------------------------------------------
template<int OB, int OE, bool DOLOC>
__device__ __forceinline__ void conv_step2(
    const float4 a, const float4 b2, const float4 c4, const float4 d4,
    const ull* __restrict__ s_wp2,     // [o][c][k] padded to 6
    const ull* __restrict__ s_wn2,
    int c, ull* accL, ull* accP)
{
    float x0[8] = {a.x, a.y, a.z, a.w, b2.x, b2.y, b2.z, b2.w};
    float x1[8] = {c4.x, c4.y, c4.z, c4.w, d4.x, d4.y, d4.z, d4.w};
    ull xp[8];
#pragma unroll
    for (int m = 0; m < 8; m++) xp[m] = pk(x0[m], x1[m]);

    if (DOLOC) {
        const ull w0 = s_wn2[c];
#pragma unroll
        for (int j = 0; j < FD; j++) accL[j] = fma2(xp[j], w0, accL[j]);
    }

#pragma unroll
    for (int o = OB; o < OE; o++) {
        const ull* wr = s_wp2 + (o * C_IN + c) * 6;
        ulonglong2 wA = *(const ulonglong2*)(wr);      // w0, w1
        ulonglong2 wB = *(const ulonglong2*)(wr + 2);  // w2, w3
        ull w4 = wr[4];
        ull w[KW] = {wA.x, wA.y, wB.x, wB.y, w4};
#pragma unroll
        for (int ww = 0; ww < 4; ww++) {
#pragma unroll
            for (int k = 0; k < KW; k++)
                accP[(o - OB) * 4 + ww] =
                    fma2(xp[ww + k], w[k], accP[(o - OB) * 4 + ww]);
        }
    }
}

// Channel loop with distance-1 prefetch (4x LDG.128 per channel: 2 tokens).
template<int OB, int OE, bool DOLOC>
__device__ __forceinline__ void conv_loop2(
    const float* __restrict__ xb,      // base of token pair row (16 floats)
    const ull* __restrict__ s_wp2,
    const ull* __restrict__ s_wn2,
    ull* accL, ull* accP)
{
    const float4* p0 = (const float4*)xb;
    float4 a = p0[0], b2 = p0[1], c4 = p0[2], d4 = p0[3];
#pragma unroll 2
    for (int c = 0; c < C_IN - 1; c++) {
        const float4* pn = (const float4*)(xb + (size_t)(c + 1) * (HEIGHT * FD));
        float4 na = pn[0], nb = pn[1], nc = pn[2], nd = pn[3];
        conv_step2<OB, OE, DOLOC>(a, b2, c4, d4, s_wp2, s_wn2, c, accL, accP);
        a = na; b2 = nb; c4 = nc; d4 = nd;
    }
    conv_step2<OB, OE, DOLOC>(a, b2, c4, d4, s_wp2, s_wn2, C_IN - 1, accL, accP);
}

// ---------------------------------------------------------------------------
// Kernel 1: fused 1x1 conv (loc) + (1,5) valid conv (sigma entries).
// Two tokens per thread (adjacent; pair never straddles a batch boundary
// since tok0 is even and H*B multiples align at 4096).
// Warp-pair output split: even warp loc + o=0..3; odd warp o=4..8.
// ---------------------------------------------------------------------------
__global__ void __launch_bounds__(256, 2) conv_kernel(
    const float* __restrict__ x,   // [B, C_IN, H, FD]
    const float* __restrict__ wn,  // [C_IN]
    const float* __restrict__ bn,  // [1]
    const float* __restrict__ wp,  // [OUTC, C_IN, 1, KW]
    const float* __restrict__ bp,  // [OUTC]
    float* __restrict__ out_loc)   // [NTOK, FD]
{
    __shared__ ull  s_wp2[OUTC * C_IN * 6];    // broadcast-packed, padded to 6
    __shared__ ull  s_wn2[C_IN];
    __shared__ float s_b[OUTC + 1];

    const int t = threadIdx.x;
    for (int i = t; i < OUTC * C_IN * KW; i += 256) {
        int oc = i / KW, k = i - oc * KW;
        float w = wp[i];
        s_wp2[oc * 6 + k] = pk(w, w);
    }
    if (t < C_IN) { float w = wn[t]; s_wn2[t] = pk(w, w); }
    if (t < OUTC) s_b[t] = bp[t];
    if (t == 0)   s_b[OUTC] = bn[0];
    __syncthreads();

    const int wid  = t >> 5;           // 0..7
    const int lane = t & 31;
    const int grp  = wid >> 1;         // token group 0..3 (64 tokens each)
    const int tok0 = (blockIdx.x * 4 + grp) * 64 + lane * 2;   // even
    const int b = tok0 >> 12;          // H = 4096
    const int h = tok0 & (HEIGHT - 1);

    const float* xb = x + (size_t)b * (C_IN * HEIGHT * FD) + (size_t)h * FD;

    if ((wid & 1) == 0) {
        // -------- even warp: loc + o0..3 (8 + 16 ULL accumulators) --------
        ull accL[FD];
        ull accP[16];
#pragma unroll
        for (int j = 0; j < FD; j++) accL[j] = 0ULL;
#pragma unroll
        for (int e = 0; e < 16; e++) accP[e] = 0ULL;

        conv_loop2<0, 4, true>(xb, s_wp2, s_wn2, accL, accP);

        const float bnv = s_b[OUTC];
        float r0[8], r1[8];
#pragma unroll
        for (int j = 0; j < FD; j++) {
            float l0, l1;
            upk(accL[j], l0, l1);
            r0[j] = softplus(l0 + bnv);
            r1[j] = softplus(l1 + bnv);
        }
        float4* lp = (float4*)(out_loc + (size_t)tok0 * FD);
        lp[0] = make_float4(r0[0], r0[1], r0[2], r0[3]);
        lp[1] = make_float4(r0[4], r0[5], r0[6], r0[7]);
        lp[2] = make_float4(r1[0], r1[1], r1[2], r1[3]);
        lp[3] = make_float4(r1[4], r1[5], r1[6], r1[7]);

#pragma unroll
        for (int o = 0; o < 4; o++) {
            float be = s_b[o];
#pragma unroll
            for (int ww = 0; ww < 4; ww++) {
                float s0, s1;
                upk(accP[o * 4 + ww], s0, s1);
                float2 sv = make_float2(softplus(s0 + be), softplus(s1 + be));
                *(float2*)(g_sigma + (size_t)(o * 4 + ww) * NTOK + tok0) = sv;
            }
        }
    } else {
        // -------- odd warp: o4..8 (20 ULL accumulators) --------
        ull accP[20];
#pragma unroll
        for (int e = 0; e < 20; e++) accP[e] = 0ULL;

        conv_loop2<4, 9, false>(xb, s_wp2, s_wn2, (ull*)nullptr, accP);

#pragma unroll
        for (int o = 4; o < OUTC; o++) {
            float be = s_b[o];
#pragma unroll
            for (int ww = 0; ww < 4; ww++) {
                float s0, s1;
                upk(accP[(o - 4) * 4 + ww], s0, s1);
                float2 sv = make_float2(softplus(s0 + be), softplus(s1 + be));
                *(float2*)(g_sigma + (size_t)(o * 4 + ww) * NTOK + tok0) = sv;
            }
        }
    }
}

// ---------------------------------------------------------------------------
// Kernel 2: batched 8x8 symmetric eigh — PARALLEL (tournament) Jacobi.
// (R15 version verbatim — best measured eigh at 47.2 us, rel_err 7.76e-5.)
// ---------------------------------------------------------------------------
#define TI(i,j) ((i) <= (j) ? ((i)*(17-(i)))/2 + ((j)-(i)) \
                            : ((j)*(17-(j)))/2 + ((i)-(j)))
#define AT(i,j) Au[TI(i,j)]

__device__ const int RR[7][4][2] = {
    {{0,7},{1,6},{2,5},{3,4}},
    {{1,7},{0,2},{3,6},{4,5}},
    {{2,7},{1,3},{0,4},{5,6}},
    {{3,7},{2,4},{1,5},{0,6}},
    {{4,7},{3,5},{2,6},{0,1}},
    {{5,7},{4,6},{0,3},{1,2}},
    {{6,7},{0,5},{1,4},{2,3}},
};

__global__ void __launch_bounds__(128) eigh_kernel(float* __restrict__ out_pd)
{
    const int tok = blockIdx.x * 128 + threadIdx.x;

    float Au[HALF];
#pragma unroll
    for (int e = 0; e < HALF; e++) Au[e] = g_sigma[(size_t)e * NTOK + tok];

    ull Vp[8][4];
#pragma unroll
    for (int c = 0; c < 8; c++)
#pragma unroll
        for (int jp = 0; jp < 4; jp++)
            Vp[c][jp] = pk((2 * jp == c) ? 1.0f : 0.0f,
                           (2 * jp + 1 == c) ? 1.0f : 0.0f);

#pragma unroll 1
    for (int sweep = 0; sweep < NSWEEP; sweep++) {
#pragma unroll
        for (int rnd = 0; rnd < 7; rnd++) {
            float cc[4], ss[4], napp[4], tr[4];
#pragma unroll
            for (int i = 0; i < 4; i++) {
                const int p = RR[rnd][i][0];
                const int q = RR[rnd][i][1];
                float apq = AT(p, q);
                float app = AT(p, p);
                float aqq = AT(q, q);
                float tau = (aqq - app);
                tau += copysignf(1e-18f, tau);
                float r2    = fmaf(tau, tau, 4.0f * apq * apq);
                float inv_r = rsqrtf(r2);
                float c2    = fmaf(0.5f * fabsf(tau), inv_r, 0.5f);
                float cinv  = rsqrtf(c2);
                cc[i]       = c2 * cinv;
                float st    = (tau < 0.0f) ? -apq : apq;
                ss[i]       = st * inv_r * cinv;
                float s2c   = 2.0f * st * inv_r;
                napp[i] = c2 * app + (1.0f - c2) * aqq - s2c * apq;
                tr[i]   = app + aqq;
            }
#pragma unroll
            for (int i = 0; i < 4; i++) {
                const int p = RR[rnd][i][0];
                const int q = RR[rnd][i][1];
                AT(p, p) = napp[i];
                AT(q, q) = tr[i] - napp[i];
                AT(p, q) = 0.0f;
#pragma unroll
                for (int j = 0; j < 8; j++) {
                    if (j == p || j == q) continue;
                    float ajp = AT(j, p), ajq = AT(j, q);
                    AT(j, p) = cc[i] * ajp - ss[i] * ajq;
                    AT(j, q) = ss[i] * ajp + cc[i] * ajq;
                }
                ull cc2  = pk(cc[i], cc[i]);
                ull ss2  = pk(ss[i], ss[i]);
                ull nss2 = pk(-ss[i], -ss[i]);
#pragma unroll
                for (int jp = 0; jp < 4; jp++) {
                    ull vp = Vp[p][jp], vq = Vp[q][jp];
                    Vp[p][jp] = fma2(nss2, vq, mul2(cc2, vp));
                    Vp[q][jp] = fma2(cc2,  vq, mul2(ss2, vp));
                }
            }
        }
    }

    float V[8][8];
#pragma unroll
    for (int c = 0; c < 8; c++)
#pragma unroll
        for (int jp = 0; jp < 4; jp++)
            upk(Vp[c][jp], V[2 * jp][c], V[2 * jp + 1][c]);

    float lam[8];
#pragma unroll
    for (int k = 0; k < 8; k++) lam[k] = fmaxf(AT(k, k), MIN_EIG);

    float W[8][8];
#pragma unroll
    for (int i = 0; i < 8; i++)
#pragma unroll
        for (int k = 0; k < 8; k++) W[i][k] = V[i][k] * lam[k];

    float pd[8][8];
#pragma unroll
    for (int i = 0; i < 8; i++) {
#pragma unroll
        for (int j = i; j < 8; j++) {
            float acc = 0.0f;
#pragma unroll
            for (int k = 0; k < 8; k++) acc = fmaf(W[i][k], V[j][k], acc);
            pd[i][j] = acc; pd[j][i] = acc;
        }
    }

    float* o = out_pd + (size_t)tok * 64;
#pragma unroll
    for (int i = 0; i < 8; i++) {
        ((float4*)o)[i * 2]     = make_float4(pd[i][0], pd[i][1], pd[i][2], pd[i][3]);
        ((float4*)o)[i * 2 + 1] = make_float4(pd[i][4], pd[i][5], pd[i][6], pd[i][7]);
    }
}

// ---------------------------------------------------------------------------
extern "C" void kernel_launch(void* const* d_in, const int* in_sizes, int n_in,
                              void* d_out, int out_size)
{
    // Identify inputs by element count (robust to metadata ordering):
    // x: 67108864, w_n: 64, b_n: 1, w_p: 2880, b_p: 9
    const float* x  = nullptr;
    const float* wn = nullptr;
    const float* bn = nullptr;
    const float* wp = nullptr;
    const float* bp = nullptr;
    for (int i = 0; i < n_in; i++) {
        switch (in_sizes[i]) {
            case 64:    wn = (const float*)d_in[i]; break;
            case 1:     bn = (const float*)d_in[i]; break;
            case 2880:  wp = (const float*)d_in[i]; break;
            case 9:     bp = (const float*)d_in[i]; break;
            default:    x  = (const float*)d_in[i]; break;
        }
    }

    float* out = (float*)d_out;
    float* loc = out;                                            // [B,1,H,FD]
    float* pd  = out + ((size_t)out_size - (size_t)NTOK * 64);   // [B,1,H,8,8]

    conv_kernel<<<NTOK / 256, 256>>>(x, wn, bn, wp, bp, loc);
    eigh_kernel<<<NTOK / 128, 128>>>(pd);
}

// round 17
// speedup vs baseline: 1.3735x; 1.3735x over previous
#include <cuda_runtime.h>
#include <math.h>

#define C_IN   64
#define FD     8
#define OUTC   9
#define KW     5
#define HEIGHT 4096
#define BATCH  32
#define NTOK   (BATCH * HEIGHT)      // 131072 tokens (b,h)
#define HALF   36
#define MIN_EIG 0.001f
#define NSWEEP 4

// SoA scratch: sigma[e][token]
__device__ float g_sigma[HALF * NTOK];

typedef unsigned long long ull;

__device__ __forceinline__ ull pk(float lo, float hi) {
    ull r; asm("mov.b64 %0, {%1, %2};" : "=l"(r) : "f"(lo), "f"(hi)); return r;
}
__device__ __forceinline__ void upk(ull v, float& lo, float& hi) {
    asm("mov.b64 {%0, %1}, %2;" : "=f"(lo), "=f"(hi) : "l"(v));
}
__device__ __forceinline__ ull fma2(ull a, ull b, ull c) {
    ull d; asm("fma.rn.f32x2 %0, %1, %2, %3;" : "=l"(d) : "l"(a), "l"(b), "l"(c)); return d;
}
__device__ __forceinline__ ull mul2(ull a, ull b) {
    ull d; asm("mul.rn.f32x2 %0, %1, %2;" : "=l"(d) : "l"(a), "l"(b)); return d;
}
__device__ __forceinline__ float softplus(float v) {
    return v > 20.0f ? v : log1pf(expf(v));
}

// ---------------------------------------------------------------------------
// Conv channel-compute: FFMA2 packed over adjacent feature positions.
// (R8/R11/R15 version verbatim — best measured conv at 97.5 us.)
// ---------------------------------------------------------------------------
template<int OB, int OE, bool DOLOC>
__device__ __forceinline__ void conv_step(
    const float4 u, const float4 v,
    const ull* __restrict__ s_wp2,     // [o][c][k] padded to 6
    const ull* __restrict__ s_wn2,
    int c, ull* accL, ull* accP)
{
    float xv[8] = {u.x, u.y, u.z, u.w, v.x, v.y, v.z, v.w};
    ull xm[7];                          // xm[m] = (x[m], x[m+1])
#pragma unroll
    for (int m = 0; m < 7; m++) xm[m] = pk(xv[m], xv[m + 1]);

    if (DOLOC) {
        const ull w0 = s_wn2[c];
#pragma unroll
        for (int j = 0; j < FD / 2; j++) accL[j] = fma2(xm[2 * j], w0, accL[j]);
    }

#pragma unroll
    for (int o = OB; o < OE; o++) {
        const ull* wr = s_wp2 + (o * C_IN + c) * 6;
        ulonglong2 wA = *(const ulonglong2*)(wr);      // w0, w1
        ulonglong2 wB = *(const ulonglong2*)(wr + 2);  // w2, w3
        ull w4 = wr[4];
        ull w[KW] = {wA.x, wA.y, wB.x, wB.y, w4};
#pragma unroll
        for (int wq = 0; wq < 2; wq++) {
#pragma unroll
            for (int k = 0; k < KW; k++)
                accP[(o - OB) * 2 + wq] =
                    fma2(xm[2 * wq + k], w[k], accP[(o - OB) * 2 + wq]);
        }
    }
}

// Pipelined channel loop: prefetch channel c+1 while computing channel c.
template<int OB, int OE, bool DOLOC>
__device__ __forceinline__ void conv_loop(
    const float* __restrict__ xb,
    const ull* __restrict__ s_wp2,
    const ull* __restrict__ s_wn2,
    ull* accL, ull* accP)
{
    const float4* p0 = (const float4*)xb;
    float4 u = p0[0];
    float4 v = p0[1];
#pragma unroll 4
    for (int c = 0; c < C_IN - 1; c++) {
        const float4* pn = (const float4*)(xb + (size_t)(c + 1) * (HEIGHT * FD));
        float4 nu = pn[0];
        float4 nv = pn[1];
        conv_step<OB, OE, DOLOC>(u, v, s_wp2, s_wn2, c, accL, accP);
        u = nu; v = nv;
    }
    conv_step<OB, OE, DOLOC>(u, v, s_wp2, s_wn2, C_IN - 1, accL, accP);
}

// ---------------------------------------------------------------------------
// Kernel 1: fused 1x1 conv (loc) + (1,5) valid conv (sigma entries).
// Warp-pair split (uniform per warp, no divergence):
//   even warp: loc + outputs o=0..3 ; odd warp: outputs o=4..8
// ---------------------------------------------------------------------------
__global__ void __launch_bounds__(256, 3) conv_kernel(
    const float* __restrict__ x,   // [B, C_IN, H, FD]
    const float* __restrict__ wn,  // [C_IN]
    const float* __restrict__ bn,  // [1]
    const float* __restrict__ wp,  // [OUTC, C_IN, 1, KW]
    const float* __restrict__ bp,  // [OUTC]
    float* __restrict__ out_loc)   // [NTOK, FD]
{
    __shared__ ull  s_wp2[OUTC * C_IN * 6];    // broadcast-packed, padded to 6
    __shared__ ull  s_wn2[C_IN];
    __shared__ float s_b[OUTC + 1];

    const int t = threadIdx.x;
    for (int i = t; i < OUTC * C_IN * KW; i += 256) {
        int oc = i / KW, k = i - oc * KW;
        float w = wp[i];
        s_wp2[oc * 6 + k] = pk(w, w);
    }
    if (t < C_IN) { float w = wn[t]; s_wn2[t] = pk(w, w); }
    if (t < OUTC) s_b[t] = bp[t];
    if (t == 0)   s_b[OUTC] = bn[0];
    __syncthreads();

    const int wid  = t >> 5;           // 0..7
    const int lane = t & 31;
    const int tok  = (blockIdx.x * 4 + (wid >> 1)) * 32 + lane;
    const int b = tok >> 12;           // H = 4096
    const int h = tok & (HEIGHT - 1);

    const float* xb = x + (size_t)b * (C_IN * HEIGHT * FD) + (size_t)h * FD;

    if ((wid & 1) == 0) {
        // ---------------- even warp: loc + o0..3 ----------------
        ull accL[FD / 2];
        ull accP[8];
#pragma unroll
        for (int j = 0; j < FD / 2; j++) accL[j] = 0ULL;
#pragma unroll
        for (int e = 0; e < 8; e++) accP[e] = 0ULL;

        conv_loop<0, 4, true>(xb, s_wp2, s_wn2, accL, accP);

        const float bnv = s_b[OUTC];
        float r[8];
#pragma unroll
        for (int j = 0; j < FD / 2; j++) {
            float a, bb;
            upk(accL[j], a, bb);
            r[2 * j]     = softplus(a + bnv);
            r[2 * j + 1] = softplus(bb + bnv);
        }
        float4* lp = (float4*)(out_loc + (size_t)tok * FD);
        lp[0] = make_float4(r[0], r[1], r[2], r[3]);
        lp[1] = make_float4(r[4], r[5], r[6], r[7]);

#pragma unroll
        for (int o = 0; o < 4; o++) {
            float be = s_b[o];
            float a, bb;
            upk(accP[o * 2], a, bb);
            g_sigma[(o * 4 + 0) * NTOK + tok] = softplus(a + be);
            g_sigma[(o * 4 + 1) * NTOK + tok] = softplus(bb + be);
            upk(accP[o * 2 + 1], a, bb);
            g_sigma[(o * 4 + 2) * NTOK + tok] = softplus(a + be);
            g_sigma[(o * 4 + 3) * NTOK + tok] = softplus(bb + be);
        }
    } else {
        // ---------------- odd warp: o4..8 ----------------
        ull accP[10];
#pragma unroll
        for (int e = 0; e < 10; e++) accP[e] = 0ULL;

        conv_loop<4, 9, false>(xb, s_wp2, s_wn2, (ull*)nullptr, accP);

#pragma unroll
        for (int o = 4; o < OUTC; o++) {
            float be = s_b[o];
            float a, bb;
            upk(accP[(o - 4) * 2], a, bb);
            g_sigma[(o * 4 + 0) * NTOK + tok] = softplus(a + be);
            g_sigma[(o * 4 + 1) * NTOK + tok] = softplus(bb + be);
            upk(accP[(o - 4) * 2 + 1], a, bb);
            g_sigma[(o * 4 + 2) * NTOK + tok] = softplus(a + be);
            g_sigma[(o * 4 + 3) * NTOK + tok] = softplus(bb + be);
        }
    }
}

// ---------------------------------------------------------------------------
// Kernel 2: batched 8x8 symmetric eigh — PARALLEL (tournament) Jacobi.
// 7 rounds x 4 disjoint pairs per sweep; angles for a round computed from
// the round-start A (commuting rotations), then applied.
// FINAL-round A off-diagonal updates are skipped (dead work: only diagonals
// feed lambda, and V carries the rotations). Identical lambda & V.
// ---------------------------------------------------------------------------
#define TI(i,j) ((i) <= (j) ? ((i)*(17-(i)))/2 + ((j)-(i)) \
                            : ((j)*(17-(j)))/2 + ((i)-(j)))
#define AT(i,j) Au[TI(i,j)]

__device__ const int RR[7][4][2] = {
    {{0,7},{1,6},{2,5},{3,4}},
    {{1,7},{0,2},{3,6},{4,5}},
    {{2,7},{1,3},{0,4},{5,6}},
    {{3,7},{2,4},{1,5},{0,6}},
    {{4,7},{3,5},{2,6},{0,1}},
    {{5,7},{4,6},{0,3},{1,2}},
    {{6,7},{0,5},{1,4},{2,3}},
};

__global__ void __launch_bounds__(128) eigh_kernel(float* __restrict__ out_pd)
{
    const int tok = blockIdx.x * 128 + threadIdx.x;

    float Au[HALF];
#pragma unroll
    for (int e = 0; e < HALF; e++) Au[e] = g_sigma[(size_t)e * NTOK + tok];

    ull Vp[8][4];
#pragma unroll
    for (int c = 0; c < 8; c++)
#pragma unroll
        for (int jp = 0; jp < 4; jp++)
            Vp[c][jp] = pk((2 * jp == c) ? 1.0f : 0.0f,
                           (2 * jp + 1 == c) ? 1.0f : 0.0f);

#pragma unroll 1
    for (int sweep = 0; sweep < NSWEEP; sweep++) {
        const bool last_sweep = (sweep == NSWEEP - 1);
#pragma unroll
        for (int rnd = 0; rnd < 7; rnd++) {
            // ---- phase 1: 4 independent angle computations (ILP x4) ----
            float cc[4], ss[4], napp[4], tr[4];
#pragma unroll
            for (int i = 0; i < 4; i++) {
                const int p = RR[rnd][i][0];
                const int q = RR[rnd][i][1];
                float apq = AT(p, q);
                float app = AT(p, p);
                float aqq = AT(q, q);
                float tau = (aqq - app);
                tau += copysignf(1e-18f, tau);          // degenerate-safe
                float r2    = fmaf(tau, tau, 4.0f * apq * apq);
                float inv_r = rsqrtf(r2);
                float c2    = fmaf(0.5f * fabsf(tau), inv_r, 0.5f); // cos^2
                float cinv  = rsqrtf(c2);
                cc[i]       = c2 * cinv;                            // cos
                float st    = (tau < 0.0f) ? -apq : apq;            // sign(tau)*apq
                ss[i]       = st * inv_r * cinv;                    // sin
                float s2c   = 2.0f * st * inv_r;                    // sin(2phi) fold
                napp[i] = c2 * app + (1.0f - c2) * aqq - s2c * apq;
                tr[i]   = app + aqq;
            }
            // ---- phase 2: apply 4 commuting two-sided rotations ----
            const bool skipA = last_sweep && (rnd == 6);  // final round: A
            //                off-diagonals are dead (only diag -> lambda)
#pragma unroll
            for (int i = 0; i < 4; i++) {
                const int p = RR[rnd][i][0];
                const int q = RR[rnd][i][1];
                AT(p, p) = napp[i];
                AT(q, q) = tr[i] - napp[i];
                if (!skipA) {
                    AT(p, q) = 0.0f;
#pragma unroll
                    for (int j = 0; j < 8; j++) {
                        if (j == p || j == q) continue;
                        float ajp = AT(j, p), ajq = AT(j, q);
                        AT(j, p) = cc[i] * ajp - ss[i] * ajq;
                        AT(j, q) = ss[i] * ajp + cc[i] * ajq;
                    }
                }
                ull cc2  = pk(cc[i], cc[i]);
                ull ss2  = pk(ss[i], ss[i]);
                ull nss2 = pk(-ss[i], -ss[i]);
#pragma unroll
                for (int jp = 0; jp < 4; jp++) {
                    ull vp = Vp[p][jp], vq = Vp[q][jp];
                    Vp[p][jp] = fma2(nss2, vq, mul2(cc2, vp));
                    Vp[q][jp] = fma2(cc2,  vq, mul2(ss2, vp));
                }
            }
        }
    }

    float V[8][8];   // V[row][col]
#pragma unroll
    for (int c = 0; c < 8; c++)
#pragma unroll
        for (int jp = 0; jp < 4; jp++)
            upk(Vp[c][jp], V[2 * jp][c], V[2 * jp + 1][c]);

    float lam[8];
#pragma unroll
    for (int k = 0; k < 8; k++) lam[k] = fmaxf(AT(k, k), MIN_EIG);

    float W[8][8];
#pragma unroll
    for (int i = 0; i < 8; i++)
#pragma unroll
        for (int k = 0; k < 8; k++) W[i][k] = V[i][k] * lam[k];

    float pd[8][8];
#pragma unroll
    for (int i = 0; i < 8; i++) {
#pragma unroll
        for (int j = i; j < 8; j++) {
            float acc = 0.0f;
#pragma unroll
            for (int k = 0; k < 8; k++) acc = fmaf(W[i][k], V[j][k], acc);
            pd[i][j] = acc; pd[j][i] = acc;
        }
    }

    float* o = out_pd + (size_t)tok * 64;
#pragma unroll
    for (int i = 0; i < 8; i++) {
        ((float4*)o)[i * 2]     = make_float4(pd[i][0], pd[i][1], pd[i][2], pd[i][3]);
        ((float4*)o)[i * 2 + 1] = make_float4(pd[i][4], pd[i][5], pd[i][6], pd[i][7]);
    }
}

// ---------------------------------------------------------------------------
extern "C" void kernel_launch(void* const* d_in, const int* in_sizes, int n_in,
                              void* d_out, int out_size)
{
    // Identify inputs by element count (robust to metadata ordering):
    // x: 67108864, w_n: 64, b_n: 1, w_p: 2880, b_p: 9
    const float* x  = nullptr;
    const float* wn = nullptr;
    const float* bn = nullptr;
    const float* wp = nullptr;
    const float* bp = nullptr;
    for (int i = 0; i < n_in; i++) {
        switch (in_sizes[i]) {
            case 64:    wn = (const float*)d_in[i]; break;
            case 1:     bn = (const float*)d_in[i]; break;
            case 2880:  wp = (const float*)d_in[i]; break;
            case 9:     bp = (const float*)d_in[i]; break;
            default:    x  = (const float*)d_in[i]; break;
        }
    }

    float* out = (float*)d_out;
    float* loc = out;                                            // [B,1,H,FD]
    float* pd  = out + ((size_t)out_size - (size_t)NTOK * 64);   // [B,1,H,8,8]

    conv_kernel<<<NTOK / 128, 256>>>(x, wn, bn, wp, bp, loc);
    eigh_kernel<<<NTOK / 128, 128>>>(pd);
}